// round 2
// baseline (speedup 1.0000x reference)
#include <cuda_runtime.h>
#include <cuda_bf16.h>

// TELIF: temporal-encoded LIF spiking neuron scan.
// tx: [T, B, N] f32, TE: [N, T] f32 -> ty: [T, B, N] f32.
//
// R2 changes vs R1:
//  - Software-pipelined double buffer: loads for step-block k+1 issue BEFORE
//    the compute chain of block k, so DRAM always has outstanding requests
//    (R1 alternated load-batch/compute -> DRAM stuck at 44%).
//  - 64-thread blocks (1024 blocks) to kill the 2-vs-1 block/SM wave
//    imbalance of the 256-block launch.
//  - __ldcs/__stcs on the pure streams (tx, out) so they don't evict the
//    64x-reused TE (2 MB) from L2.

#define T_STEPS 512
#define B_DIM   64
#define N_DIM   1024
#define BN      (B_DIM * N_DIM)

#define REST      0.0f
#define DECAY     0.2f
#define THRESHOLD 0.3f
#define BETA      0.02f

__device__ float g_te_t[T_STEPS * N_DIM];  // TE transposed to [T][N]

// ---------------------------------------------------------------------------
// Transpose TE [N, T] -> g_te_t [T, N]. 32x32 tiles, padded smem.
// ---------------------------------------------------------------------------
__global__ void telif_transpose_te(const float* __restrict__ TE) {
    __shared__ float tile[32][33];
    int n0 = blockIdx.x * 32;
    int t0 = blockIdx.y * 32;
    int lx = threadIdx.x;
    int ly = threadIdx.y;

#pragma unroll
    for (int i = 0; i < 32; i += 8)
        tile[ly + i][lx] = TE[(size_t)(n0 + ly + i) * T_STEPS + (t0 + lx)];
    __syncthreads();
#pragma unroll
    for (int i = 0; i < 32; i += 8)
        g_te_t[(size_t)(t0 + ly + i) * N_DIM + (n0 + lx)] = tile[lx][ly + i];
}

// ---------------------------------------------------------------------------
// Main scan. One thread per (b, n); 64-thread blocks; pipelined unroll 8x2.
// ---------------------------------------------------------------------------
#define LOAD8(buf_x, buf_t, tbase)                                             \
    _Pragma("unroll")                                                          \
    for (int u = 0; u < 8; u++) {                                              \
        buf_x[u] = __ldcs(txp + (size_t)((tbase) + u) * BN);                   \
        buf_t[u] = __ldg(tep + (size_t)((tbase) + u) * N_DIM);                 \
    }

#define COMPUTE8(buf_x, buf_t, tbase)                                          \
    _Pragma("unroll")                                                          \
    for (int u = 0; u < 8; u++) {                                              \
        th = th + v * buf_t[u] - (th - THRESHOLD) * BETA;                      \
        v  = v * DECAY * (1.0f - y) + buf_x[u];                                \
        y  = (v > th) ? 1.0f : 0.0f;                                           \
        __stcs(op + (size_t)((tbase) + u) * BN, y);                            \
    }

__global__ void __launch_bounds__(64)
telif_scan(const float* __restrict__ tx, float* __restrict__ out) {
    const int idx = blockIdx.x * 64 + threadIdx.x;   // b*N + n
    const int n   = idx & (N_DIM - 1);

    const float* txp = tx + idx;
    float*       op  = out + idx;
    const float* tep = g_te_t + n;

    float v  = REST;
    float y  = 0.0f;
    float th = THRESHOLD;

    float xa[8], ta[8], xb[8], tb[8];

    // Prologue: fill buffer A with steps 0..7.
    LOAD8(xa, ta, 0)

#pragma unroll 1
    for (int t0 = 0; t0 < T_STEPS; t0 += 16) {
        // Prefetch B (t0+8..t0+15) before consuming A.
        LOAD8(xb, tb, t0 + 8)
        COMPUTE8(xa, ta, t0)

        // Prefetch A for next iteration (t0+16..t0+23) before consuming B.
        if (t0 + 16 < T_STEPS) {
            LOAD8(xa, ta, t0 + 16)
        }
        COMPUTE8(xb, tb, t0 + 8)
    }
}

// ---------------------------------------------------------------------------
// Launch
// ---------------------------------------------------------------------------
extern "C" void kernel_launch(void* const* d_in, const int* in_sizes, int n_in,
                              void* d_out, int out_size) {
    const float* tx = (const float*)d_in[0];   // [T, B, N]
    const float* TE = (const float*)d_in[1];   // [N, T]
    float* out = (float*)d_out;                // [T, B, N]

    (void)in_sizes; (void)n_in; (void)out_size;

    dim3 tb(32, 8);
    dim3 tg(N_DIM / 32, T_STEPS / 32);
    telif_transpose_te<<<tg, tb>>>(TE);

    telif_scan<<<BN / 64, 64>>>(tx, out);
}

// round 3
// speedup vs baseline: 1.0320x; 1.0320x over previous
#include <cuda_runtime.h>
#include <cuda_bf16.h>

// TELIF: temporal-encoded LIF spiking neuron scan.
// tx: [T, B, N] f32, TE: [N, T] f32 -> ty: [T, B, N] f32.
//
// R3 changes vs R1 (R2's pipeline/.cs/block-64 combo regressed and is reverted):
//  - float2: 2 neurons per thread. Doubles bytes-in-flight per outstanding
//    load (LDG.64) and gives ILP=2 across the two independent recurrence
//    chains. 32768 threads, 1024 blocks of 32 -> 6.92 blocks/SM, balanced.
//  - Front-batch 16 steps of loads (64 buffer regs) before the compute chain;
//    simple load-then-compute shape that R1 showed works.

#define T_STEPS 512
#define B_DIM   64
#define N_DIM   1024
#define BN      (B_DIM * N_DIM)

#define REST      0.0f
#define DECAY     0.2f
#define THRESHOLD 0.3f
#define BETA      0.02f

#define UNROLL 16

__device__ float g_te_t[T_STEPS * N_DIM];  // TE transposed to [T][N]

// ---------------------------------------------------------------------------
// Transpose TE [N, T] -> g_te_t [T, N]. 32x32 tiles, padded smem.
// ---------------------------------------------------------------------------
__global__ void telif_transpose_te(const float* __restrict__ TE) {
    __shared__ float tile[32][33];
    int n0 = blockIdx.x * 32;
    int t0 = blockIdx.y * 32;
    int lx = threadIdx.x;
    int ly = threadIdx.y;

#pragma unroll
    for (int i = 0; i < 32; i += 8)
        tile[ly + i][lx] = TE[(size_t)(n0 + ly + i) * T_STEPS + (t0 + lx)];
    __syncthreads();
#pragma unroll
    for (int i = 0; i < 32; i += 8)
        g_te_t[(size_t)(t0 + ly + i) * N_DIM + (n0 + lx)] = tile[lx][ly + i];
}

// ---------------------------------------------------------------------------
// Main scan. One thread per 2 adjacent (b, n) lanes; float2 everywhere.
// ---------------------------------------------------------------------------
__global__ void __launch_bounds__(32)
telif_scan(const float2* __restrict__ tx2, float2* __restrict__ out2) {
    const int gid = blockIdx.x * 32 + threadIdx.x;      // pair index
    const int n2  = gid & (N_DIM / 2 - 1);              // pair index within N

    const float2* txp = tx2 + gid;
    float2*       op  = out2 + gid;
    const float2* tep = reinterpret_cast<const float2*>(g_te_t) + n2;

    float vx = REST, vy = REST;
    float yx = 0.0f, yy = 0.0f;
    float thx = THRESHOLD, thy = THRESHOLD;

#pragma unroll 1
    for (int t0 = 0; t0 < T_STEPS; t0 += UNROLL) {
        float2 xs[UNROLL], te[UNROLL];
        // Front-batched independent loads: 32 outstanding LDG.64 per thread.
#pragma unroll
        for (int u = 0; u < UNROLL; u++) {
            xs[u] = txp[(size_t)(t0 + u) * (BN / 2)];
            te[u] = tep[(size_t)(t0 + u) * (N_DIM / 2)];
        }
        // Two independent chains (x / y lanes) -> ILP 2 on the serial path.
#pragma unroll
        for (int u = 0; u < UNROLL; u++) {
            thx = thx + vx * te[u].x - (thx - THRESHOLD) * BETA;
            thy = thy + vy * te[u].y - (thy - THRESHOLD) * BETA;
            vx  = vx * DECAY * (1.0f - yx) + xs[u].x;
            vy  = vy * DECAY * (1.0f - yy) + xs[u].y;
            yx  = (vx > thx) ? 1.0f : 0.0f;
            yy  = (vy > thy) ? 1.0f : 0.0f;
            float2 o; o.x = yx; o.y = yy;
            op[(size_t)(t0 + u) * (BN / 2)] = o;
        }
    }
}

// ---------------------------------------------------------------------------
// Launch
// ---------------------------------------------------------------------------
extern "C" void kernel_launch(void* const* d_in, const int* in_sizes, int n_in,
                              void* d_out, int out_size) {
    const float* tx = (const float*)d_in[0];   // [T, B, N]
    const float* TE = (const float*)d_in[1];   // [N, T]
    float* out = (float*)d_out;                // [T, B, N]

    (void)in_sizes; (void)n_in; (void)out_size;

    dim3 tb(32, 8);
    dim3 tg(N_DIM / 32, T_STEPS / 32);
    telif_transpose_te<<<tg, tb>>>(TE);

    telif_scan<<<(BN / 2) / 32, 32>>>(
        reinterpret_cast<const float2*>(tx),
        reinterpret_cast<float2*>(out));
}